// round 5
// baseline (speedup 1.0000x reference)
#include <cuda_runtime.h>
#include <cuda_bf16.h>
#include <math.h>

#define HIDDEN 2048
#define NEXP   8
#define TOK_PER_WARP 2
#define WARPS_PER_BLOCK 8
#define TOK_PER_BLOCK (TOK_PER_WARP * WARPS_PER_BLOCK)   // 16

// ---------------------------------------------------------------------------
// Packed fp32x2 FMA (sm_100+). ptxas never auto-fuses 2x fmaf into FFMA2;
// only PTX fma.rn.f32x2 reaches the double-rate fp32 path.
// ---------------------------------------------------------------------------
__device__ __forceinline__ void ffma2(unsigned long long& acc,
                                      unsigned long long a,
                                      unsigned long long b) {
    asm("fma.rn.f32x2 %0, %1, %2, %0;" : "+l"(acc) : "l"(a), "l"(b));
}

__device__ __forceinline__ float2 unpack_f32x2(unsigned long long v) {
    float2 r;
    asm("mov.b64 {%0, %1}, %2;" : "=f"(r.x), "=f"(r.y) : "l"(v));
    return r;
}

// Reference-matching sigmoid: XLA GPU computes 1/(1+exp(-x)) in fp32 with
// FTZ enabled. Consequences we must reproduce exactly (they define the
// tie-sets that top_k's stable index-order tie-break acts on):
//   x >  16.636 : exactly 1.0f              (1+exp(-x) rounds to 1.0)
//   x < -87.336 : exactly 0.0f              (result subnormal -> FTZ, and
//                                            exp(-x)=inf below -88.72)
//   else        : distinct normal values, monotone in x
__device__ __forceinline__ float ref_sigmoid(float x) {
    float s = 1.0f / (1.0f + expf(-x));
    if (s < 1.17549435e-38f) s = 0.0f;   // flush subnormal results (FTZ)
    return s;
}

// ---------------------------------------------------------------------------
// Router kernel: warp computes 8 expert sigmoid scores for 2 tokens,
// full stable descending sort (top_k == n_experts), normalize, scale.
// ---------------------------------------------------------------------------
__global__ __launch_bounds__(256)
void moe_router_kernel(const float* __restrict__ x,      // [N, HIDDEN]
                       const float* __restrict__ w,      // [NEXP, HIDDEN]
                       const float* __restrict__ bias,   // [NEXP]
                       float* __restrict__ out_w,        // [N, NEXP]
                       float* __restrict__ out_i,        // [N, NEXP] (indices as float) or null
                       int N) {
    // transpose-reduce scratch: [warp][lane][16 partials], pad 17 -> conflict-free
    __shared__ float red[WARPS_PER_BLOCK][32][TOK_PER_WARP * NEXP + 1];

    const int warp = threadIdx.x >> 5;
    const int lane = threadIdx.x & 31;
    const int tok0 = (blockIdx.x * WARPS_PER_BLOCK + warp) * TOK_PER_WARP;
    if (tok0 >= N) return;

    // x / w viewed as packed fp32 pairs (ull); 16B vector loads (LDG.128)
    const unsigned long long* xp0 = reinterpret_cast<const unsigned long long*>(
        x + (size_t)tok0 * HIDDEN);
    const unsigned long long* xp1 = xp0 + (HIDDEN / 2);
    const unsigned long long* wp  = reinterpret_cast<const unsigned long long*>(w);

    unsigned long long acc[TOK_PER_WARP][NEXP];
#pragma unroll
    for (int t = 0; t < TOK_PER_WARP; t++)
#pragma unroll
        for (int e = 0; e < NEXP; e++) acc[t][e] = 0ull;

    // Each iteration: lane covers 4 consecutive floats (2 packed pairs).
    // 16 iterations x 32 lanes x 4 floats = 2048 = HIDDEN.
#pragma unroll 2
    for (int i = 0; i < 16; i++) {
        const int p = (i * 32 + lane) * 2;  // offset in pair units
        ulonglong2 xa = *reinterpret_cast<const ulonglong2*>(xp0 + p);
        ulonglong2 xb = *reinterpret_cast<const ulonglong2*>(xp1 + p);
#pragma unroll
        for (int e = 0; e < NEXP; e++) {
            ulonglong2 we = *reinterpret_cast<const ulonglong2*>(
                wp + (size_t)e * (HIDDEN / 2) + p);
            ffma2(acc[0][e], xa.x, we.x);
            ffma2(acc[0][e], xa.y, we.y);
            ffma2(acc[1][e], xb.x, we.x);
            ffma2(acc[1][e], xb.y, we.y);
        }
    }

    // per-lane partial sums -> smem transpose
#pragma unroll
    for (int t = 0; t < TOK_PER_WARP; t++)
#pragma unroll
        for (int e = 0; e < NEXP; e++) {
            float2 v = unpack_f32x2(acc[t][e]);
            red[warp][lane][t * NEXP + e] = v.x + v.y;
        }
    __syncwarp();

    // lanes 0..15: one (token, expert) each. Sum 32 lane-partials.
    if (lane < TOK_PER_WARP * NEXP) {
        const int t = lane >> 3;
        const int e = lane & 7;

        float logit = 0.0f;
#pragma unroll
        for (int j = 0; j < 32; j++) logit += red[warp][j][lane];

        float score = ref_sigmoid(logit);
        float sel   = score + bias[e];

        // sum of all 8 scores within the 8-lane token group
        const unsigned int amask = 0x0000FFFFu;
        float tot = score;
        tot += __shfl_xor_sync(amask, tot, 4);
        tot += __shfl_xor_sync(amask, tot, 2);
        tot += __shfl_xor_sync(amask, tot, 1);

        // stable descending rank: count (greater) or (equal with lower index)
        const int base = lane & 8;  // group start lane
        int rank = 0;
#pragma unroll
        for (int j = 0; j < NEXP; j++) {
            float sj = __shfl_sync(amask, sel, base + j);
            rank += (sj > sel) || (sj == sel && j < e);
        }

        const float wv = (score / (tot + 1e-10f)) * 1.4f;
        const int tg = tok0 + t;
        out_w[(size_t)tg * NEXP + rank] = wv;
        if (out_i) out_i[(size_t)tg * NEXP + rank] = (float)e;
    }
}

// ---------------------------------------------------------------------------
// Harness entry
// ---------------------------------------------------------------------------
extern "C" void kernel_launch(void* const* d_in, const int* in_sizes, int n_in,
                              void* d_out, int out_size) {
    const float* x    = (const float*)d_in[0];   // hidden_states [4,8192,2048]
    const float* w    = (const float*)d_in[1];   // weight [8,2048]
    const float* bias = (const float*)d_in[2];   // e_score_correction_bias [8]

    const int N = in_sizes[0] / HIDDEN;          // 32768 tokens

    float* ow = (float*)d_out;                   // weights [N,8]
    float* oi = nullptr;                         // indices [N,8] as float
    if (out_size >= 2 * N * NEXP) oi = ow + (size_t)N * NEXP;

    dim3 grid((N + TOK_PER_BLOCK - 1) / TOK_PER_BLOCK);
    moe_router_kernel<<<grid, 256>>>(x, w, bias, ow, oi, N);
}

// round 6
// speedup vs baseline: 1.2131x; 1.2131x over previous
#include <cuda_runtime.h>
#include <cuda_bf16.h>
#include <math.h>

#define HIDDEN 2048
#define NEXP   8
#define TOK_PER_WARP 4
#define WARPS_PER_BLOCK 8
#define TOK_PER_BLOCK (TOK_PER_WARP * WARPS_PER_BLOCK)   // 32

// ---------------------------------------------------------------------------
// Packed fp32x2 FMA (sm_100+). ptxas never auto-fuses 2x fmaf into FFMA2;
// only PTX fma.rn.f32x2 reaches the double-rate fp32 path.
// ---------------------------------------------------------------------------
__device__ __forceinline__ void ffma2(unsigned long long& acc,
                                      unsigned long long a,
                                      unsigned long long b) {
    asm("fma.rn.f32x2 %0, %1, %2, %0;" : "+l"(acc) : "l"(a), "l"(b));
}

__device__ __forceinline__ float2 unpack_f32x2(unsigned long long v) {
    float2 r;
    asm("mov.b64 {%0, %1}, %2;" : "=f"(r.x), "=f"(r.y) : "l"(v));
    return r;
}

// Reference-matching sigmoid: 1/(1+exp(-x)) in fp32 with FTZ semantics.
// Tie-sets (which top_k's stable index-order tie-break acts on):
//   x >  16.636 : exactly 1.0f
//   x < -87.336 : exactly 0.0f (subnormal result flushed / exp overflow)
// Verified in R5: index output matched exactly under this model.
__device__ __forceinline__ float ref_sigmoid(float x) {
    float s = 1.0f / (1.0f + expf(-x));
    if (s < 1.17549435e-38f) s = 0.0f;   // flush subnormal results (FTZ)
    return s;
}

// ---------------------------------------------------------------------------
// Router kernel: warp computes 8 expert sigmoid scores for 4 tokens,
// full stable descending sort (top_k == n_experts), normalize, scale.
// TOK_PER_WARP=4 halves the per-token weight-matrix refetch (L1 wavefront
// bound in R5: 320 wf/token -> 192 wf/token, pushing the kernel DRAM-bound).
// ---------------------------------------------------------------------------
__global__ __launch_bounds__(256, 2)
void moe_router_kernel(const float* __restrict__ x,      // [N, HIDDEN]
                       const float* __restrict__ w,      // [NEXP, HIDDEN]
                       const float* __restrict__ bias,   // [NEXP]
                       float* __restrict__ out_w,        // [N, NEXP]
                       float* __restrict__ out_i,        // [N, NEXP] (indices as float) or null
                       int N) {
    // transpose-reduce scratch: [warp][lane][32 partials], pad 33 -> conflict-free
    __shared__ float red[WARPS_PER_BLOCK][32][TOK_PER_WARP * NEXP + 1];

    const int warp = threadIdx.x >> 5;
    const int lane = threadIdx.x & 31;
    const int tok0 = (blockIdx.x * WARPS_PER_BLOCK + warp) * TOK_PER_WARP;
    if (tok0 >= N) return;

    // x / w viewed as packed fp32 pairs (ull); 16B vector loads (LDG.128)
    const unsigned long long* xp0 = reinterpret_cast<const unsigned long long*>(
        x + (size_t)tok0 * HIDDEN);
    const unsigned long long* xp1 = xp0 + (HIDDEN / 2);
    const unsigned long long* xp2 = xp0 + 2 * (HIDDEN / 2);
    const unsigned long long* xp3 = xp0 + 3 * (HIDDEN / 2);
    const unsigned long long* wp  = reinterpret_cast<const unsigned long long*>(w);

    unsigned long long acc[TOK_PER_WARP][NEXP];
#pragma unroll
    for (int t = 0; t < TOK_PER_WARP; t++)
#pragma unroll
        for (int e = 0; e < NEXP; e++) acc[t][e] = 0ull;

    // Each iteration: lane covers 4 consecutive floats (2 packed pairs).
    // 16 iterations x 32 lanes x 4 floats = 2048 = HIDDEN.
#pragma unroll 2
    for (int i = 0; i < 16; i++) {
        const int p = (i * 32 + lane) * 2;  // offset in pair units
        ulonglong2 xa = *reinterpret_cast<const ulonglong2*>(xp0 + p);
        ulonglong2 xb = *reinterpret_cast<const ulonglong2*>(xp1 + p);
        ulonglong2 xc = *reinterpret_cast<const ulonglong2*>(xp2 + p);
        ulonglong2 xd = *reinterpret_cast<const ulonglong2*>(xp3 + p);
#pragma unroll
        for (int e = 0; e < NEXP; e++) {
            ulonglong2 we = *reinterpret_cast<const ulonglong2*>(
                wp + (size_t)e * (HIDDEN / 2) + p);
            ffma2(acc[0][e], xa.x, we.x);
            ffma2(acc[0][e], xa.y, we.y);
            ffma2(acc[1][e], xb.x, we.x);
            ffma2(acc[1][e], xb.y, we.y);
            ffma2(acc[2][e], xc.x, we.x);
            ffma2(acc[2][e], xc.y, we.y);
            ffma2(acc[3][e], xd.x, we.x);
            ffma2(acc[3][e], xd.y, we.y);
        }
    }

    // per-lane partial sums -> smem transpose
#pragma unroll
    for (int t = 0; t < TOK_PER_WARP; t++)
#pragma unroll
        for (int e = 0; e < NEXP; e++) {
            float2 v = unpack_f32x2(acc[t][e]);
            red[warp][lane][t * NEXP + e] = v.x + v.y;
        }
    __syncwarp();

    // all 32 lanes: one (token, expert) each. Sum 32 lane-partials.
    {
        const int t = lane >> 3;
        const int e = lane & 7;

        float logit = 0.0f;
#pragma unroll
        for (int j = 0; j < 32; j++) logit += red[warp][j][lane];

        float score = ref_sigmoid(logit);
        float sel   = score + bias[e];

        // sum of all 8 scores within each aligned 8-lane token group
        const unsigned int amask = 0xFFFFFFFFu;
        float tot = score;
        tot += __shfl_xor_sync(amask, tot, 4);
        tot += __shfl_xor_sync(amask, tot, 2);
        tot += __shfl_xor_sync(amask, tot, 1);

        // stable descending rank: count (greater) or (equal with lower index)
        const int base = lane & 24;  // group start lane
        int rank = 0;
#pragma unroll
        for (int j = 0; j < NEXP; j++) {
            float sj = __shfl_sync(amask, sel, base + j);
            rank += (sj > sel) || (sj == sel && j < e);
        }

        const float wv = (score / (tot + 1e-10f)) * 1.4f;
        const int tg = tok0 + t;
        out_w[(size_t)tg * NEXP + rank] = wv;
        if (out_i) out_i[(size_t)tg * NEXP + rank] = (float)e;
    }
}

// ---------------------------------------------------------------------------
// Harness entry
// ---------------------------------------------------------------------------
extern "C" void kernel_launch(void* const* d_in, const int* in_sizes, int n_in,
                              void* d_out, int out_size) {
    const float* x    = (const float*)d_in[0];   // hidden_states [4,8192,2048]
    const float* w    = (const float*)d_in[1];   // weight [8,2048]
    const float* bias = (const float*)d_in[2];   // e_score_correction_bias [8]

    const int N = in_sizes[0] / HIDDEN;          // 32768 tokens

    float* ow = (float*)d_out;                   // weights [N,8]
    float* oi = nullptr;                         // indices [N,8] as float
    if (out_size >= 2 * N * NEXP) oi = ow + (size_t)N * NEXP;

    dim3 grid((N + TOK_PER_BLOCK - 1) / TOK_PER_BLOCK);
    moe_router_kernel<<<grid, 256>>>(x, w, bias, ow, oi, N);
}